// round 6
// baseline (speedup 1.0000x reference)
#include <cuda_runtime.h>
#include <cuda_fp16.h>

// PointWarping2 — Nadaraya-Watson Gaussian regression (exact f32 math).
// Query-pair f32x2 packing, 8 queries per thread (4 packed pairs) so MUFU ex2
// is the only near-saturated pipe (issue slack ~30%). Split-K (MSPLIT=32).
// Finalize: 1 thread/query, 32 independent vectorized loads (MLP-bound).
//
// w' = ex2( q . a_xyz + a_w ), a = (2L*y, -L*|y|^2), L = log2(e)/s^2
// (per-query factor 2^{L|q|^2} cancels in num/den — exact).

#define Bx 2
#define N1x 8192
#define N2x 8192
#define NQ (Bx * N2x)           // 16384 queries
#define MSPLIT 32
#define TILE 256                 // sources per split
#define BLK 128
#define NPAIR 4                  // query-pairs per thread
#define QPT (2 * NPAIR)          // 8 queries per thread
#define QPB (BLK * QPT)          // 1024 queries per block
#define PCHUNK (QPB / NPAIR)     // 256: query offset between a thread's pairs

typedef unsigned long long ull;

__device__ float4 g_partial[MSPLIT * NQ];

__device__ __forceinline__ float ex2f(float x) {
    float y;
    asm("ex2.approx.ftz.f32 %0, %1;" : "=f"(y) : "f"(x));
    return y;
}
__device__ __forceinline__ ull fma2(ull a, ull b, ull c) {
    ull d;
    asm("fma.rn.f32x2 %0, %1, %2, %3;" : "=l"(d) : "l"(a), "l"(b), "l"(c));
    return d;
}
__device__ __forceinline__ ull add2(ull a, ull b) {
    ull d;
    asm("add.rn.f32x2 %0, %1, %2;" : "=l"(d) : "l"(a), "l"(b));
    return d;
}
__device__ __forceinline__ ull pack2(float lo, float hi) {
    ull d;
    asm("mov.b64 %0, {%1, %2};" : "=l"(d) : "f"(lo), "f"(hi));
    return d;
}
__device__ __forceinline__ void unpack2(ull v, float& lo, float& hi) {
    asm("mov.b64 {%0, %1}, %2;" : "=f"(lo), "=f"(hi) : "l"(v));
}

// resol_factor may arrive as int32 or float32 bits; disambiguate.
__device__ __forceinline__ float read_scale(const void* p) {
    int iv = *(const int*)p;
    float f;
    if (iv > 0 && iv < 100000) f = (float)iv;
    else f = __int_as_float(iv);
    return 1.0f * f;  // INITIAL_RADIUS = 1.0
}

__global__ __launch_bounds__(BLK) void main_kernel(
    const float* __restrict__ xyz1, const float* __restrict__ xyz2,
    const float* __restrict__ flow1, const void* __restrict__ resol) {
    // duplicated source data: (ax,ax,ay,ay) (az,az,aw,aw) (fx,fx,fy,fy) (fz,fz)
    __shared__ float4 s0[TILE];
    __shared__ float4 s1[TILE];
    __shared__ float4 s2[TILE];
    __shared__ float2 s3[TILE];

    int qbase = blockIdx.x * QPB;           // block stays within one batch
    int b = qbase >> 13;
    float scale = read_scale(resol);
    float L = 1.4426950408889634f / (scale * scale);
    float t2 = 2.0f * L;

    // ---- fused prep: build duplicated source tile from raw inputs ----
    const float* x1b = xyz1 + b * 3 * N1x;
    const float* f1b = flow1 + b * 3 * N1x;
    int m0 = blockIdx.y * TILE;
    #pragma unroll
    for (int i = threadIdx.x; i < TILE; i += BLK) {
        int m = m0 + i;
        float fx = f1b[m], fy = f1b[N1x + m], fz = f1b[2 * N1x + m];
        float yx = x1b[m] + fx;
        float yy = x1b[N1x + m] + fy;
        float yz = x1b[2 * N1x + m] + fz;
        float ax = t2 * yx, ay = t2 * yy, az = t2 * yz;
        float aw = -L * (yx * yx + yy * yy + yz * yz);
        s0[i] = make_float4(ax, ax, ay, ay);
        s1[i] = make_float4(az, az, aw, aw);
        s2[i] = make_float4(fx, fx, fy, fy);
        s3[i] = make_float2(fz, fz);
    }

    // ---- query-pair registers: NPAIR pairs per thread ----
    const float* x2b = xyz2 + b * 3 * N2x;
    ull qx2[NPAIR], qy2[NPAIR], qz2[NPAIR];
    #pragma unroll
    for (int p = 0; p < NPAIR; p++) {
        int n = ((qbase + 2 * threadIdx.x + p * PCHUNK) & (N2x - 1));
        float2 vx = *(const float2*)(x2b + n);
        float2 vy = *(const float2*)(x2b + N2x + n);
        float2 vz = *(const float2*)(x2b + 2 * N2x + n);
        qx2[p] = pack2(vx.x, vx.y);
        qy2[p] = pack2(vy.x, vy.y);
        qz2[p] = pack2(vz.x, vz.y);
    }

    __syncthreads();

    const ulonglong2* u0 = (const ulonglong2*)s0;
    const ulonglong2* u1 = (const ulonglong2*)s1;
    const ulonglong2* u2 = (const ulonglong2*)s2;
    const ull*        u3 = (const ull*)s3;

    ull nx[NPAIR], ny[NPAIR], nz[NPAIR], dn[NPAIR];
    #pragma unroll
    for (int p = 0; p < NPAIR; p++) { nx[p] = ny[p] = nz[p] = dn[p] = 0; }

    #pragma unroll 4
    for (int j = 0; j < TILE; j++) {
        ulonglong2 a01 = u0[j];   // (ax,ax), (ay,ay)
        ulonglong2 a23 = u1[j];   // (az,az), (aw,aw)
        ulonglong2 f01 = u2[j];   // (fx,fx), (fy,fy)
        ull        fz2 = u3[j];   // (fz,fz)
        #pragma unroll
        for (int p = 0; p < NPAIR; p++) {
            ull arg = fma2(qx2[p], a01.x,
                      fma2(qy2[p], a01.y,
                      fma2(qz2[p], a23.x, a23.y)));
            float lo, hi;
            unpack2(arg, lo, hi);
            ull w = pack2(ex2f(lo), ex2f(hi));
            nx[p] = fma2(w, f01.x, nx[p]);
            ny[p] = fma2(w, f01.y, ny[p]);
            nz[p] = fma2(w, fz2,   nz[p]);
            dn[p] = add2(dn[p], w);
        }
    }

    #pragma unroll
    for (int p = 0; p < NPAIR; p++) {
        int q = qbase + 2 * threadIdx.x + p * PCHUNK;
        float4 r0, r1;
        unpack2(nx[p], r0.x, r1.x);
        unpack2(ny[p], r0.y, r1.y);
        unpack2(nz[p], r0.z, r1.z);
        unpack2(dn[p], r0.w, r1.w);
        g_partial[blockIdx.y * NQ + q]     = r0;
        g_partial[blockIdx.y * NQ + q + 1] = r1;
    }
}

__global__ void finalize_kernel(const float* __restrict__ xyz2,
                                float* __restrict__ out) {
    int q = blockIdx.x * blockDim.x + threadIdx.x;   // one thread per query
    if (q >= NQ) return;

    // 32 independent coalesced float4 loads (MLP ~32), then sum tree.
    float4 v[MSPLIT];
    #pragma unroll
    for (int s = 0; s < MSPLIT; s++) v[s] = g_partial[s * NQ + q];
    #pragma unroll
    for (int d = MSPLIT / 2; d >= 1; d >>= 1) {
        #pragma unroll
        for (int s = 0; s < 16; s++) {
            if (s < d) {
                v[s].x += v[s + d].x;
                v[s].y += v[s + d].y;
                v[s].z += v[s + d].z;
                v[s].w += v[s + d].w;
            }
        }
    }

    int b = q >> 13;
    int n = q & (N2x - 1);
    float inv = 1.0f / v[0].w;
    const float* x2b = xyz2 + b * 3 * N2x;
    float* ob = out + b * 3 * N2x;
    ob[0 * N2x + n] = x2b[0 * N2x + n] - v[0].x * inv;
    ob[1 * N2x + n] = x2b[1 * N2x + n] - v[0].y * inv;
    ob[2 * N2x + n] = x2b[2 * N2x + n] - v[0].z * inv;
}

extern "C" void kernel_launch(void* const* d_in, const int* in_sizes, int n_in,
                              void* d_out, int out_size) {
    const float* xyz1  = (const float*)d_in[0];
    const float* xyz2  = (const float*)d_in[1];
    const float* flow1 = (const float*)d_in[2];
    const void*  resol = d_in[3];
    float* out = (float*)d_out;

    dim3 grid(NQ / QPB, MSPLIT);   // 16 x 32 = 512 blocks
    main_kernel<<<grid, BLK>>>(xyz1, xyz2, flow1, resol);

    finalize_kernel<<<(NQ + 127) / 128, 128>>>(xyz2, out);
}

// round 7
// speedup vs baseline: 1.2254x; 1.2254x over previous
#include <cuda_runtime.h>
#include <cuda_fp16.h>

// PointWarping2 — Nadaraya-Watson Gaussian regression (exact f32 math).
// R3 main config (best measured) + fused last-block reduction:
//   - f32x2-packed FMA over source pairs, 2 queries per thread
//   - split-K MSPLIT=16, 1024 blocks (28 warps/SM)
//   - last block per query-column reduces partials and writes output
//     (no separate finalize kernel; counter uses mod trick, no reset needed)
//
// w' = ex2( q . a_xyz + a_w ), a = (2L*y, -L*|y|^2), L = log2(e)/s^2
// (per-query factor 2^{L|q|^2} cancels in num/den — exact).

#define Bx 2
#define N1x 8192
#define N2x 8192
#define NQ (Bx * N2x)           // 16384 queries
#define MSPLIT 16
#define TILE 512                 // sources per split
#define PAIRS (TILE / 2)         // 256 packed source-pairs per tile
#define BLK 128
#define QPT 2                    // queries per thread
#define QPB (BLK * QPT)          // 256 queries per block
#define GRIDX (NQ / QPB)         // 64 query columns

typedef unsigned long long ull;

__device__ float4 g_partial[MSPLIT * NQ];
__device__ unsigned g_count[GRIDX];   // zero-init at load; mod trick, never reset

__device__ __forceinline__ float ex2f(float x) {
    float y;
    asm("ex2.approx.ftz.f32 %0, %1;" : "=f"(y) : "f"(x));
    return y;
}
__device__ __forceinline__ ull fma2(ull a, ull b, ull c) {
    ull d;
    asm("fma.rn.f32x2 %0, %1, %2, %3;" : "=l"(d) : "l"(a), "l"(b), "l"(c));
    return d;
}
__device__ __forceinline__ ull add2(ull a, ull b) {
    ull d;
    asm("add.rn.f32x2 %0, %1, %2;" : "=l"(d) : "l"(a), "l"(b));
    return d;
}
__device__ __forceinline__ ull pack2(float lo, float hi) {
    ull d;
    asm("mov.b64 %0, {%1, %2};" : "=l"(d) : "f"(lo), "f"(hi));
    return d;
}
__device__ __forceinline__ void unpack2(ull v, float& lo, float& hi) {
    asm("mov.b64 {%0, %1}, %2;" : "=f"(lo), "=f"(hi) : "l"(v));
}

// resol_factor may arrive as int32 or float32 bits; disambiguate.
__device__ __forceinline__ float read_scale(const void* p) {
    int iv = *(const int*)p;
    float f;
    if (iv > 0 && iv < 100000) f = (float)iv;
    else f = __int_as_float(iv);
    return 1.0f * f;  // INITIAL_RADIUS = 1.0
}

__global__ __launch_bounds__(BLK) void main_kernel(
    const float* __restrict__ xyz1, const float* __restrict__ xyz2,
    const float* __restrict__ flow1, const void* __restrict__ resol,
    float* __restrict__ out) {
    __shared__ float4 s0[PAIRS];   // (ax0,ax1, ay0,ay1)
    __shared__ float4 s1[PAIRS];   // (az0,az1, aw0,aw1)
    __shared__ float4 s2[PAIRS];   // (fx0,fx1, fy0,fy1)
    __shared__ float2 s3[PAIRS];   // (fz0,fz1)
    __shared__ unsigned s_old;

    int qbase = blockIdx.x * QPB;          // block stays within one batch
    int b = qbase >> 13;
    int q0 = qbase + threadIdx.x;
    int q1 = q0 + BLK;
    int n0 = q0 & (N2x - 1);
    int n1 = q1 & (N2x - 1);

    float scale = read_scale(resol);
    float L = 1.4426950408889634f / (scale * scale);
    float t2 = 2.0f * L;

    // ---- fused prep: build packed source tile from raw inputs ----
    const float* x1b = xyz1 + b * 3 * N1x;
    const float* f1b = flow1 + b * 3 * N1x;
    int m0 = blockIdx.y * TILE;
    #pragma unroll
    for (int i = threadIdx.x; i < PAIRS; i += BLK) {
        int m = m0 + 2 * i;
        float2 xx = *(const float2*)(x1b + m);
        float2 xy = *(const float2*)(x1b + N1x + m);
        float2 xz = *(const float2*)(x1b + 2 * N1x + m);
        float2 fx = *(const float2*)(f1b + m);
        float2 fy = *(const float2*)(f1b + N1x + m);
        float2 fz = *(const float2*)(f1b + 2 * N1x + m);
        float yx0 = xx.x + fx.x, yx1 = xx.y + fx.y;
        float yy0 = xy.x + fy.x, yy1 = xy.y + fy.y;
        float yz0 = xz.x + fz.x, yz1 = xz.y + fz.y;
        s0[i] = make_float4(t2 * yx0, t2 * yx1, t2 * yy0, t2 * yy1);
        s1[i] = make_float4(t2 * yz0, t2 * yz1,
                            -L * (yx0 * yx0 + yy0 * yy0 + yz0 * yz0),
                            -L * (yx1 * yx1 + yy1 * yy1 + yz1 * yz1));
        s2[i] = make_float4(fx.x, fx.y, fy.x, fy.y);
        s3[i] = make_float2(fz.x, fz.y);
    }

    // ---- query registers (2 queries per thread) ----
    const float* x2b = xyz2 + b * 3 * N2x;
    float qx0 = x2b[n0], qy0 = x2b[N2x + n0], qz0 = x2b[2 * N2x + n0];
    float qx1 = x2b[n1], qy1 = x2b[N2x + n1], qz1 = x2b[2 * N2x + n1];
    ull qx20 = pack2(qx0, qx0), qy20 = pack2(qy0, qy0), qz20 = pack2(qz0, qz0);
    ull qx21 = pack2(qx1, qx1), qy21 = pack2(qy1, qy1), qz21 = pack2(qz1, qz1);

    __syncthreads();

    const ulonglong2* u0 = (const ulonglong2*)s0;
    const ulonglong2* u1 = (const ulonglong2*)s1;
    const ulonglong2* u2 = (const ulonglong2*)s2;
    const ull*        u3 = (const ull*)s3;

    ull nx0 = 0, ny0 = 0, nz0 = 0, d0 = 0;
    ull nx1 = 0, ny1 = 0, nz1 = 0, d1 = 0;

    #pragma unroll 8
    for (int j = 0; j < PAIRS; j++) {
        ulonglong2 a01 = u0[j];   // ax2, ay2
        ulonglong2 a23 = u1[j];   // az2, aw2
        ulonglong2 f01 = u2[j];   // fx2, fy2
        ull        fz2 = u3[j];
        ull arg0 = fma2(qx20, a01.x, fma2(qy20, a01.y, fma2(qz20, a23.x, a23.y)));
        ull arg1 = fma2(qx21, a01.x, fma2(qy21, a01.y, fma2(qz21, a23.x, a23.y)));
        float al, ah;
        unpack2(arg0, al, ah);
        ull w0 = pack2(ex2f(al), ex2f(ah));
        unpack2(arg1, al, ah);
        ull w1 = pack2(ex2f(al), ex2f(ah));
        nx0 = fma2(w0, f01.x, nx0);
        ny0 = fma2(w0, f01.y, ny0);
        nz0 = fma2(w0, fz2, nz0);
        d0  = add2(d0, w0);
        nx1 = fma2(w1, f01.x, nx1);
        ny1 = fma2(w1, f01.y, ny1);
        nz1 = fma2(w1, fz2, nz1);
        d1  = add2(d1, w1);
    }

    {
        float a, c;
        float4 r0, r1;
        unpack2(nx0, a, c); r0.x = a + c;
        unpack2(ny0, a, c); r0.y = a + c;
        unpack2(nz0, a, c); r0.z = a + c;
        unpack2(d0,  a, c); r0.w = a + c;
        unpack2(nx1, a, c); r1.x = a + c;
        unpack2(ny1, a, c); r1.y = a + c;
        unpack2(nz1, a, c); r1.z = a + c;
        unpack2(d1,  a, c); r1.w = a + c;
        g_partial[blockIdx.y * NQ + q0] = r0;
        g_partial[blockIdx.y * NQ + q1] = r1;
    }

    // ---- last-block reduction for this query column ----
    __threadfence();
    if (threadIdx.x == 0)
        s_old = atomicAdd(&g_count[blockIdx.x], 1u);
    __syncthreads();
    if ((s_old % MSPLIT) != (MSPLIT - 1)) return;

    // This block is the last of the MSPLIT splits for query column blockIdx.x.
    const float* x2o = xyz2 + b * 3 * N2x;
    float* ob = out + b * 3 * N2x;
    #pragma unroll
    for (int k = 0; k < QPT; k++) {
        int q = qbase + threadIdx.x + k * BLK;
        float4 v[MSPLIT];
        #pragma unroll
        for (int s = 0; s < MSPLIT; s++) v[s] = g_partial[s * NQ + q];
        #pragma unroll
        for (int d = MSPLIT / 2; d >= 1; d >>= 1) {
            #pragma unroll
            for (int s = 0; s < MSPLIT / 2; s++) {
                if (s < d) {
                    v[s].x += v[s + d].x;
                    v[s].y += v[s + d].y;
                    v[s].z += v[s + d].z;
                    v[s].w += v[s + d].w;
                }
            }
        }
        int n = q & (N2x - 1);
        float inv = 1.0f / v[0].w;
        ob[0 * N2x + n] = x2o[0 * N2x + n] - v[0].x * inv;
        ob[1 * N2x + n] = x2o[1 * N2x + n] - v[0].y * inv;
        ob[2 * N2x + n] = x2o[2 * N2x + n] - v[0].z * inv;
    }
}

extern "C" void kernel_launch(void* const* d_in, const int* in_sizes, int n_in,
                              void* d_out, int out_size) {
    const float* xyz1  = (const float*)d_in[0];
    const float* xyz2  = (const float*)d_in[1];
    const float* flow1 = (const float*)d_in[2];
    const void*  resol = d_in[3];
    float* out = (float*)d_out;

    dim3 grid(GRIDX, MSPLIT);   // 64 x 16 = 1024 blocks
    main_kernel<<<grid, BLK>>>(xyz1, xyz2, flow1, resol, out);
}